// round 12
// baseline (speedup 1.0000x reference)
#include <cuda_runtime.h>
#include <cuda_bf16.h>
#include <cstdint>

#define D      512
#define NWAY   64
#define KSHOT  16
#define MAXQ   8192
#define SA     72            // smem K-stride (bf16): 144B rows, LDSM conflict-free
#define ASZ    (128 * SA)
#define BSZ    (64 * SA)
#define PA     (64 * SA)
#define PB     (128 * SA)

// ---------------- device scratch ----------------
__device__ __nv_bfloat16  g_smeanbf[NWAY * D];
__device__ float          g_Ppart[8 * NWAY * D];      // split-K P partials (fp32)
__device__ float          g_Rpart[8 * NWAY * D];      // split-K R partials (fp32)
__device__ float          g_pcpart[8 * NWAY];         // pcterm partials per j-chunk
__device__ __nv_bfloat16  g_qbf[(size_t)MAXQ * D];
__device__ __nv_bfloat16  g_Bbig[(512 + NWAY) * D];   // rows 0..511 W(bf16), 512..575 R
__device__ __nv_bfloat16  g_WbfT[D * D];              // WbfT[k, j] = W[j, k]
__device__ float          g_partial[(size_t)MAXQ * 8];
__device__ float          g_cross[(size_t)MAXQ * NWAY];

// ---------------- mma / ldmatrix / cp.async helpers ----------------
__device__ __forceinline__ void mma16816(float* c,
                                         uint32_t a0, uint32_t a1, uint32_t a2, uint32_t a3,
                                         uint32_t b0, uint32_t b1) {
    asm volatile(
        "mma.sync.aligned.m16n8k16.row.col.f32.bf16.bf16.f32 "
        "{%0,%1,%2,%3},{%4,%5,%6,%7},{%8,%9},{%0,%1,%2,%3};\n"
        : "+f"(c[0]), "+f"(c[1]), "+f"(c[2]), "+f"(c[3])
        : "r"(a0), "r"(a1), "r"(a2), "r"(a3), "r"(b0), "r"(b1));
}
__device__ __forceinline__ void ldsm4(uint32_t* r, uint32_t a) {
    asm volatile("ldmatrix.sync.aligned.m8n8.x4.shared.b16 {%0,%1,%2,%3}, [%4];"
                 : "=r"(r[0]), "=r"(r[1]), "=r"(r[2]), "=r"(r[3]) : "r"(a));
}
__device__ __forceinline__ void cp_async16(void* smem, const void* gmem) {
    uint32_t s = (uint32_t)__cvta_generic_to_shared(smem);
    asm volatile("cp.async.cg.shared.global [%0], [%1], 16;\n" :: "r"(s), "l"(gmem));
}
#define CP_COMMIT() asm volatile("cp.async.commit_group;\n")
#define CP_WAIT(n)  asm volatile("cp.async.wait_group %0;\n" :: "n"(n))

// One K=64 slab of a 32x32 warp tile: 2 m-frags x 4 n-frags, ldmatrix-fed.
__device__ __forceinline__ void tile_step(float acc[2][4][4], uint32_t aA, uint32_t aB,
                                          int aOff0, int aOff1, int bOff0, int bOff1) {
    #pragma unroll
    for (int kk = 0; kk < 64; kk += 16) {
        uint32_t br0[4], br1[4];
        ldsm4(br0, aB + bOff0 + kk * 2);
        ldsm4(br1, aB + bOff1 + kk * 2);
        #pragma unroll
        for (int mf = 0; mf < 2; mf++) {
            uint32_t ar[4];
            ldsm4(ar, aA + (mf ? aOff1 : aOff0) + kk * 2);
            mma16816(acc[mf][0], ar[0], ar[1], ar[2], ar[3], br0[0], br0[1]);
            mma16816(acc[mf][1], ar[0], ar[1], ar[2], ar[3], br0[2], br0[3]);
            mma16816(acc[mf][2], ar[0], ar[1], ar[2], ar[3], br1[0], br1[1]);
            mma16816(acc[mf][3], ar[0], ar[1], ar[2], ar[3], br1[2], br1[3]);
        }
    }
}

// ---------------- prep_q: Q -> bf16 (bulk, stream 0) ----------------
__global__ void prep_q_kernel(const float* __restrict__ q, int M) {
    size_t total = (size_t)M * D;
    size_t base = (size_t)blockIdx.x * 2048 + threadIdx.x * 8;
    if (base + 8 <= total) {
        float4 v0 = *(const float4*)(q + base);
        float4 v1 = *(const float4*)(q + base + 4);
        __nv_bfloat162 p0 = __floats2bfloat162_rn(v0.x, v0.y);
        __nv_bfloat162 p1 = __floats2bfloat162_rn(v0.z, v0.w);
        __nv_bfloat162 p2 = __floats2bfloat162_rn(v1.x, v1.y);
        __nv_bfloat162 p3 = __floats2bfloat162_rn(v1.z, v1.w);
        uint4 o;
        o.x = *(uint32_t*)&p0; o.y = *(uint32_t*)&p1;
        o.z = *(uint32_t*)&p2; o.w = *(uint32_t*)&p3;
        *(uint4*)(g_qbf + base) = o;
    } else {
        for (int e = 0; e < 8; e++)
            if (base + e < total) g_qbf[base + e] = __float2bfloat16(q[base + e]);
    }
}

// ---------------- prep_w: W->bf16, W^T, smean (side stream) ----------------
__global__ void prep_w_kernel(const float* __restrict__ W,
                              const float* __restrict__ support) {
    int b = blockIdx.x;
    int tid = threadIdx.x;
    if (b < 256) {
        int base = b * 1024 + tid * 4;
        float4 v = *(const float4*)(W + base);
        *(__nv_bfloat162*)(g_Bbig + base)     = __floats2bfloat162_rn(v.x, v.y);
        *(__nv_bfloat162*)(g_Bbig + base + 2) = __floats2bfloat162_rn(v.z, v.w);
    } else if (b < 256 + 64) {
        // W transpose 64x64 -> g_WbfT
        __shared__ float ts[64][68];
        int t = b - 256;
        int r0 = (t >> 3) * 64, c0 = (t & 7) * 64;
        #pragma unroll
        for (int it = 0; it < 4; it++) {
            int r = (tid >> 4) + it * 16;
            float4 v = *(const float4*)(W + (size_t)(r0 + r) * D + c0 + (tid & 15) * 4);
            ts[r][(tid & 15) * 4 + 0] = v.x; ts[r][(tid & 15) * 4 + 1] = v.y;
            ts[r][(tid & 15) * 4 + 2] = v.z; ts[r][(tid & 15) * 4 + 3] = v.w;
        }
        __syncthreads();
        int kk = tid >> 2, jb = (tid & 3) * 16;
        #pragma unroll
        for (int e = 0; e < 16; e += 2) {
            *(__nv_bfloat162*)(g_WbfT + (size_t)(c0 + kk) * D + r0 + jb + e) =
                __floats2bfloat162_rn(ts[jb + e][kk], ts[jb + e + 1][kk]);
        }
    } else {
        // class means -> bf16
        int c = b - 256 - 64;
        for (int col = tid; col < D; col += blockDim.x) {
            float s = 0.f;
            #pragma unroll
            for (int k = 0; k < KSHOT; k++) s += support[(size_t)(c * KSHOT + k) * D + col];
            g_smeanbf[c * D + col] = __float2bfloat16(s * (1.f / KSHOT));
        }
    }
}

// ---------------- proj: Ppart[ks] = smeanbf @ W^T (one 64-k chunk per block) ----------------
__global__ __launch_bounds__(256) void proj_gemm(int dummy) {
    __shared__ __nv_bfloat16 sA[PA];
    __shared__ __nv_bfloat16 sB[PB];
    int tid = threadIdx.x;
    int n0 = blockIdx.x * 128;    // j tile
    int ks = blockIdx.y;          // k chunk
    int warp = tid >> 5, lane = tid & 31;
    int wm = warp & 1, wn = warp >> 1;
    int g = lane >> 2, t4 = lane & 3;

    int aOff0 = (((wm * 32 + 0 + (lane & 15)) * SA + (lane >> 4) * 8)) * 2;
    int aOff1 = (((wm * 32 + 16 + (lane & 15)) * SA + (lane >> 4) * 8)) * 2;
    int bOff0 = (((wn * 32 + 0 + (lane & 7) + ((lane >> 4) << 3)) * SA + ((lane >> 3) & 1) * 8)) * 2;
    int bOff1 = (((wn * 32 + 16 + (lane & 7) + ((lane >> 4) << 3)) * SA + ((lane >> 3) & 1) * 8)) * 2;

    #pragma unroll
    for (int j = 0; j < 2; j++) {
        int i = tid + j * 256, r = i >> 3, c8 = i & 7;
        cp_async16(sA + r * SA + c8 * 8, g_smeanbf + (size_t)r * D + ks * 64 + c8 * 8);
    }
    #pragma unroll
    for (int j = 0; j < 4; j++) {
        int i = tid + j * 256, r = i >> 3, c8 = i & 7;
        cp_async16(sB + r * SA + c8 * 8, g_Bbig + (size_t)(n0 + r) * D + ks * 64 + c8 * 8);
    }
    CP_COMMIT();

    float acc[2][4][4];
    #pragma unroll
    for (int a = 0; a < 2; a++)
        #pragma unroll
        for (int b2 = 0; b2 < 4; b2++)
            #pragma unroll
            for (int c = 0; c < 4; c++) acc[a][b2][c] = 0.f;

    CP_WAIT(0); __syncthreads();
    tile_step(acc, (uint32_t)__cvta_generic_to_shared(sA),
              (uint32_t)__cvta_generic_to_shared(sB), aOff0, aOff1, bOff0, bOff1);

    float* cp = g_Ppart + (size_t)ks * NWAY * D;
    #pragma unroll
    for (int mf = 0; mf < 2; mf++) {
        int m = wm * 32 + mf * 16 + g;
        #pragma unroll
        for (int nf = 0; nf < 4; nf++) {
            int c = n0 + wn * 32 + nf * 8 + t4 * 2;
            float2 o0; o0.x = acc[mf][nf][0]; o0.y = acc[mf][nf][1];
            float2 o1; o1.x = acc[mf][nf][2]; o1.y = acc[mf][nf][3];
            *(float2*)(cp + (size_t)m * D + c) = o0;
            *(float2*)(cp + (size_t)(m + 8) * D + c) = o1;
        }
    }
}

// ---------------- r2: Rpart[js] = P @ W over j-chunk; builds P from Ppart+bias in-kernel ----------------
__global__ __launch_bounds__(256) void r2_gemm(const float* __restrict__ bias) {
    __shared__ __nv_bfloat16 sA[PA];
    __shared__ __nv_bfloat16 sB[PB];
    int tid = threadIdx.x;
    int n0 = blockIdx.x * 128;    // k-col tile of R
    int js = blockIdx.y;          // j chunk
    int warp = tid >> 5, lane = tid & 31;
    int wm = warp & 1, wn = warp >> 1;
    int g = lane >> 2, t4 = lane & 3;

    int aOff0 = (((wm * 32 + 0 + (lane & 15)) * SA + (lane >> 4) * 8)) * 2;
    int aOff1 = (((wm * 32 + 16 + (lane & 15)) * SA + (lane >> 4) * 8)) * 2;
    int bOff0 = (((wn * 32 + 0 + (lane & 7) + ((lane >> 4) << 3)) * SA + ((lane >> 3) & 1) * 8)) * 2;
    int bOff1 = (((wn * 32 + 16 + (lane & 7) + ((lane >> 4) << 3)) * SA + ((lane >> 3) & 1) * 8)) * 2;

    #pragma unroll
    for (int j = 0; j < 4; j++) {
        int i = tid + j * 256, r = i >> 3, c8 = i & 7;
        cp_async16(sB + r * SA + c8 * 8, g_WbfT + (size_t)(n0 + r) * D + js * 64 + c8 * 8);
    }
    CP_COMMIT();

    // Build A tile: P[row][j] = sum_{kp} Ppart[kp][row][j] + bias[j]
    int row = tid >> 2, jq = (tid & 3) * 16;
    float pc = 0.f;
    #pragma unroll
    for (int g4 = 0; g4 < 4; g4++) {
        int j = js * 64 + jq + g4 * 4;
        float4 v = *(const float4*)(bias + j);
        #pragma unroll
        for (int kp = 0; kp < 8; kp++) {
            const float4 pp = *(const float4*)(g_Ppart + (size_t)kp * NWAY * D + (size_t)row * D + j);
            v.x += pp.x; v.y += pp.y; v.z += pp.z; v.w += pp.w;
        }
        float4 b4 = *(const float4*)(bias + j);
        pc += v.x * (v.x - 2.f * b4.x) + v.y * (v.y - 2.f * b4.y)
            + v.z * (v.z - 2.f * b4.z) + v.w * (v.w - 2.f * b4.w);
        *(__nv_bfloat162*)(sA + row * SA + jq + g4 * 4)     = __floats2bfloat162_rn(v.x, v.y);
        *(__nv_bfloat162*)(sA + row * SA + jq + g4 * 4 + 2) = __floats2bfloat162_rn(v.z, v.w);
    }
    if (blockIdx.x == 0) {
        pc += __shfl_xor_sync(0xffffffffu, pc, 1);
        pc += __shfl_xor_sync(0xffffffffu, pc, 2);
        if ((tid & 3) == 0) g_pcpart[js * NWAY + row] = pc;
    }

    float acc[2][4][4];
    #pragma unroll
    for (int a = 0; a < 2; a++)
        #pragma unroll
        for (int b2 = 0; b2 < 4; b2++)
            #pragma unroll
            for (int c = 0; c < 4; c++) acc[a][b2][c] = 0.f;

    CP_WAIT(0); __syncthreads();
    tile_step(acc, (uint32_t)__cvta_generic_to_shared(sA),
              (uint32_t)__cvta_generic_to_shared(sB), aOff0, aOff1, bOff0, bOff1);

    float* cp = g_Rpart + (size_t)js * NWAY * D;
    #pragma unroll
    for (int mf = 0; mf < 2; mf++) {
        int m = wm * 32 + mf * 16 + g;
        #pragma unroll
        for (int nf = 0; nf < 4; nf++) {
            int c = n0 + wn * 32 + nf * 8 + t4 * 2;
            float2 o0; o0.x = acc[mf][nf][0]; o0.y = acc[mf][nf][1];
            float2 o1; o1.x = acc[mf][nf][2]; o1.y = acc[mf][nf][3];
            *(float2*)(cp + (size_t)m * D + c) = o0;
            *(float2*)(cp + (size_t)(m + 8) * D + c) = o1;
        }
    }
}

// ---------------- rred: R = sum(8 Rpart) -> bf16; grid (64 classes, 4 k-quarters) ----------------
__global__ void rred_kernel(int dummy) {
    int c = blockIdx.x;
    int k = blockIdx.y * 128 + threadIdx.x;
    float v = 0.f;
    #pragma unroll
    for (int js = 0; js < 8; js++)
        v += g_Rpart[(size_t)js * NWAY * D + (size_t)c * D + k];
    g_Bbig[(size_t)(512 + c) * D + k] = __float2bfloat16(v);
}

// ---------------- main GEMM: C = Qbf @ Bbig^T, LDSM-fed, 4-stage cp.async ----------------
#define SM_BIAS  (4 * (ASZ + BSZ) * 2)
#define SM_NORM  (SM_BIAS + 64 * 4)
#define SM_MAIN  (SM_NORM + 128 * 2 * 4)

__global__ __launch_bounds__(256, 2) void main_gemm(const float* __restrict__ bias, int M,
                                                    int ntbase) {
    extern __shared__ char smc[];
    __nv_bfloat16* sA = (__nv_bfloat16*)smc;
    __nv_bfloat16* sB = (__nv_bfloat16*)smc + 4 * ASZ;
    float* sbias = (float*)(smc + SM_BIAS);
    float* snorm = (float*)(smc + SM_NORM);

    int tid = threadIdx.x;
    int m0 = blockIdx.x * 128;
    int nt = ntbase + blockIdx.y;
    int n0 = nt * 64;
    int warp = tid >> 5, lane = tid & 31;
    int wm = warp & 3, wn = warp >> 2;
    int g = lane >> 2, t4 = lane & 3;

    if (nt < 8 && tid < 64) sbias[tid] = bias[n0 + tid];

    int aOff0 = (((wm * 32 + 0 + (lane & 15)) * SA + (lane >> 4) * 8)) * 2;
    int aOff1 = (((wm * 32 + 16 + (lane & 15)) * SA + (lane >> 4) * 8)) * 2;
    int bOff0 = (((wn * 32 + 0 + (lane & 7) + ((lane >> 4) << 3)) * SA + ((lane >> 3) & 1) * 8)) * 2;
    int bOff1 = (((wn * 32 + 16 + (lane & 7) + ((lane >> 4) << 3)) * SA + ((lane >> 3) & 1) * 8)) * 2;

    float acc[2][4][4];
    #pragma unroll
    for (int a = 0; a < 2; a++)
        #pragma unroll
        for (int b2 = 0; b2 < 4; b2++)
            #pragma unroll
            for (int c = 0; c < 4; c++) acc[a][b2][c] = 0.f;

    auto loadA = [&](int st, int kt) {
        #pragma unroll
        for (int j = 0; j < 4; j++) {
            int i = tid + j * 256, r = i >> 3, c8 = i & 7;
            int grow = m0 + r; if (grow >= M) grow = M - 1;
            cp_async16(sA + st * ASZ + r * SA + c8 * 8,
                       g_qbf + (size_t)grow * D + kt * 64 + c8 * 8);
        }
    };
    auto loadB = [&](int st, int kt) {
        #pragma unroll
        for (int j = 0; j < 2; j++) {
            int i = tid + j * 256, r = i >> 3, c8 = i & 7;
            cp_async16(sB + st * BSZ + r * SA + c8 * 8,
                       g_Bbig + (size_t)(n0 + r) * D + kt * 64 + c8 * 8);
        }
    };

    loadA(0, 0); loadB(0, 0); CP_COMMIT();
    loadA(1, 1); loadB(1, 1); CP_COMMIT();
    loadA(2, 2); loadB(2, 2); CP_COMMIT();

    uint32_t sa0 = (uint32_t)__cvta_generic_to_shared(sA);
    uint32_t sb0 = (uint32_t)__cvta_generic_to_shared(sB);

    #pragma unroll 1
    for (int kt = 0; kt < 8; kt++) {
        if (kt < 6) { CP_WAIT(2); } else if (kt == 6) { CP_WAIT(1); } else { CP_WAIT(0); }
        __syncthreads();
        if (kt + 3 < 8) { loadA((kt + 3) & 3, kt + 3); loadB((kt + 3) & 3, kt + 3); CP_COMMIT(); }
        tile_step(acc, sa0 + ((kt & 3) * ASZ) * 2, sb0 + ((kt & 3) * BSZ) * 2,
                  aOff0, aOff1, bOff0, bOff1);
    }

    if (nt < 8) {
        #pragma unroll
        for (int mf = 0; mf < 2; mf++) {
            float s0 = 0.f, s1 = 0.f;
            #pragma unroll
            for (int nf = 0; nf < 4; nf++) {
                int c = wn * 32 + nf * 8 + t4 * 2;
                float b0 = sbias[c], b1 = sbias[c + 1];
                float v;
                v = acc[mf][nf][0] + b0; s0 += v * v;
                v = acc[mf][nf][1] + b1; s0 += v * v;
                v = acc[mf][nf][2] + b0; s1 += v * v;
                v = acc[mf][nf][3] + b1; s1 += v * v;
            }
            s0 += __shfl_xor_sync(0xffffffffu, s0, 1);
            s0 += __shfl_xor_sync(0xffffffffu, s0, 2);
            s1 += __shfl_xor_sync(0xffffffffu, s1, 1);
            s1 += __shfl_xor_sync(0xffffffffu, s1, 2);
            if (t4 == 0) {
                int r = wm * 32 + mf * 16 + g;
                snorm[r * 2 + wn] = s0;
                snorm[(r + 8) * 2 + wn] = s1;
            }
        }
        __syncthreads();
        if (tid < 128 && m0 + tid < M)
            g_partial[(size_t)(m0 + tid) * 8 + nt] = snorm[tid * 2] + snorm[tid * 2 + 1];
    } else {
        #pragma unroll
        for (int mf = 0; mf < 2; mf++) {
            int r = wm * 32 + mf * 16 + g;
            #pragma unroll
            for (int nf = 0; nf < 4; nf++) {
                int c = wn * 32 + nf * 8 + t4 * 2;
                if (m0 + r < M) {
                    float2 o; o.x = acc[mf][nf][0]; o.y = acc[mf][nf][1];
                    *(float2*)(g_cross + (size_t)(m0 + r) * NWAY + c) = o;
                }
                if (m0 + r + 8 < M) {
                    float2 o; o.x = acc[mf][nf][2]; o.y = acc[mf][nf][3];
                    *(float2*)(g_cross + (size_t)(m0 + r + 8) * NWAY + c) = o;
                }
            }
        }
    }
}

// ---------------- combine: dist = nq + pcterm - 2*cross ----------------
__global__ void combine_kernel(float* __restrict__ out, int M) {
    __shared__ float snq[4];
    int tid = threadIdx.x;
    int q0 = blockIdx.x * 4;
    if (tid < 4 && q0 + tid < M) {
        float s = 0.f;
        #pragma unroll
        for (int t = 0; t < 8; t++) s += g_partial[(size_t)(q0 + tid) * 8 + t];
        snq[tid] = s;
    }
    __syncthreads();
    int q = q0 + (tid >> 6), c = tid & 63;
    if (q < M) {
        float pc = 0.f;
        #pragma unroll
        for (int js = 0; js < 8; js++) pc += g_pcpart[js * NWAY + c];
        out[(size_t)q * NWAY + c] = snq[tid >> 6] + pc
                                    - 2.f * g_cross[(size_t)q * NWAY + c];
    }
}

// ---------------- launch ----------------
extern "C" void kernel_launch(void* const* d_in, const int* in_sizes, int n_in,
                              void* d_out, int out_size) {
    const float* support = (const float*)d_in[0];
    const float* query   = (const float*)d_in[1];
    const float* W       = (const float*)d_in[2];
    const float* bias    = (const float*)d_in[3];
    int M = in_sizes[1] / D;
    if (M > MAXQ) M = MAXQ;
    float* out = (float*)d_out;
    int mblocks = (M + 127) / 128;
    int qblocks = (int)(((size_t)M * D + 2047) / 2048);

    cudaFuncSetAttribute(main_gemm, cudaFuncAttributeMaxDynamicSharedMemorySize, SM_MAIN);

    cudaStream_t s2 = 0;
    cudaEvent_t eStart = 0, eQ = 0, eW = 0, eX = 0;
    bool par = (cudaStreamCreateWithFlags(&s2, cudaStreamNonBlocking) == cudaSuccess);
    if (par) par = (cudaEventCreateWithFlags(&eStart, cudaEventDisableTiming) == cudaSuccess);
    if (par) par = (cudaEventCreateWithFlags(&eQ, cudaEventDisableTiming) == cudaSuccess);
    if (par) par = (cudaEventCreateWithFlags(&eW, cudaEventDisableTiming) == cudaSuccess);
    if (par) par = (cudaEventCreateWithFlags(&eX, cudaEventDisableTiming) == cudaSuccess);

    if (par) {
        // s0: prep_q -> eQ; wait eW; norm; wait eX; combine
        // s2: wait eStart; prep_w -> eW; proj; r2; rred; wait eQ; cross -> eX
        cudaEventRecord(eStart, 0);
        cudaStreamWaitEvent(s2, eStart, 0);

        prep_q_kernel<<<qblocks, 256>>>(query, M);
        cudaEventRecord(eQ, 0);

        prep_w_kernel<<<256 + 64 + 64, 256, 0, s2>>>(W, support);
        cudaEventRecord(eW, s2);
        proj_gemm<<<dim3(4, 8), 256, 0, s2>>>(0);
        r2_gemm<<<dim3(4, 8), 256, 0, s2>>>(bias);
        rred_kernel<<<dim3(NWAY, 4), 128, 0, s2>>>(0);
        cudaStreamWaitEvent(s2, eQ, 0);
        main_gemm<<<dim3(mblocks, 1), 256, SM_MAIN, s2>>>(bias, M, 8);  // cross (overlaps norm)
        cudaEventRecord(eX, s2);

        cudaStreamWaitEvent(0, eW, 0);
        main_gemm<<<dim3(mblocks, 8), 256, SM_MAIN>>>(bias, M, 0);       // norm
        cudaStreamWaitEvent(0, eX, 0);
        combine_kernel<<<(M + 3) / 4, 256>>>(out, M);
    } else {
        prep_q_kernel<<<qblocks, 256>>>(query, M);
        prep_w_kernel<<<256 + 64 + 64, 256>>>(W, support);
        proj_gemm<<<dim3(4, 8), 256>>>(0);
        r2_gemm<<<dim3(4, 8), 256>>>(bias);
        rred_kernel<<<dim3(NWAY, 4), 128>>>(0);
        main_gemm<<<dim3(mblocks, 8), 256, SM_MAIN>>>(bias, M, 0);
        main_gemm<<<dim3(mblocks, 1), 256, SM_MAIN>>>(bias, M, 8);
        combine_kernel<<<(M + 3) / 4, 256>>>(out, M);
    }
}